// round 1
// baseline (speedup 1.0000x reference)
#include <cuda_runtime.h>

#define BATCHES 4
#define MBOX    128
#define TPB     256
#define PPT     4

__global__ __launch_bounds__(TPB)
void pib_kernel(const float* __restrict__ pts,
                const float* __restrict__ boxes,
                float* __restrict__ out,
                int N)
{
    // Box data in shared, SoA as two float4 per box:
    //   sA[m] = (cx, cy, cos, sin)
    //   sB[m] = (hx, hy, cz, hz)   (h = half dims)
    __shared__ float4 sA[MBOX];
    __shared__ float4 sB[MBOX];

    const int blocks_per_batch = gridDim.x / BATCHES;
    const int b   = blockIdx.x / blocks_per_batch;
    const int blk = blockIdx.x % blocks_per_batch;
    const int t   = threadIdx.x;

    if (t < MBOX) {
        const float* bx = boxes + ((size_t)b * MBOX + t) * 7;
        float cx = bx[0], cy = bx[1], cz = bx[2];
        float dxs = bx[3], dys = bx[4], dzs = bx[5];
        float rz = bx[6];
        float s, c;
        __sincosf(rz, &s, &c);
        sA[t] = make_float4(cx, cy, c, s);
        sB[t] = make_float4(0.5f * dxs, 0.5f * dys, cz, 0.5f * dzs);
    }
    __syncthreads();

    // 4 points per thread, contiguous, loaded as 3x float4 (48B, 16B-aligned)
    const int i0 = (blk * TPB + t) * PPT;
    const float4* p4 = reinterpret_cast<const float4*>(pts + ((size_t)b * N + i0) * 3);
    float4 q0 = p4[0], q1 = p4[1], q2 = p4[2];
    float x0 = q0.x, y0 = q0.y, z0 = q0.z;
    float x1 = q0.w, y1 = q1.x, z1 = q1.y;
    float x2 = q1.z, y2 = q1.w, z2 = q2.x;
    float x3 = q2.y, y3 = q2.z, z3 = q2.w;

    int r0 = -1, r1 = -1, r2 = -1, r3 = -1;

    // Descending scan: last hit written wins == smallest box index ==
    // "first containing box". One SEL per test, branchless.
    #pragma unroll 2
    for (int m = MBOX - 1; m >= 0; --m) {
        float4 A  = sA[m];
        float4 Bv = sB[m];
        float c = A.z, s = A.w;
        {
            float dx = x0 - A.x, dy = y0 - A.y, dz = z0 - Bv.z;
            float lx = dx * c + dy * s;
            float ly = dy * c - dx * s;
            bool in = (fabsf(lx) <= Bv.x) & (fabsf(ly) <= Bv.y) & (fabsf(dz) <= Bv.w);
            r0 = in ? m : r0;
        }
        {
            float dx = x1 - A.x, dy = y1 - A.y, dz = z1 - Bv.z;
            float lx = dx * c + dy * s;
            float ly = dy * c - dx * s;
            bool in = (fabsf(lx) <= Bv.x) & (fabsf(ly) <= Bv.y) & (fabsf(dz) <= Bv.w);
            r1 = in ? m : r1;
        }
        {
            float dx = x2 - A.x, dy = y2 - A.y, dz = z2 - Bv.z;
            float lx = dx * c + dy * s;
            float ly = dy * c - dx * s;
            bool in = (fabsf(lx) <= Bv.x) & (fabsf(ly) <= Bv.y) & (fabsf(dz) <= Bv.w);
            r2 = in ? m : r2;
        }
        {
            float dx = x3 - A.x, dy = y3 - A.y, dz = z3 - Bv.z;
            float lx = dx * c + dy * s;
            float ly = dy * c - dx * s;
            bool in = (fabsf(lx) <= Bv.x) & (fabsf(ly) <= Bv.y) & (fabsf(dz) <= Bv.w);
            r3 = in ? m : r3;
        }
    }

    float4 o = make_float4((float)r0, (float)r1, (float)r2, (float)r3);
    *reinterpret_cast<float4*>(out + (size_t)b * N + i0) = o;
}

extern "C" void kernel_launch(void* const* d_in, const int* in_sizes, int n_in,
                              void* d_out, int out_size)
{
    const float* pts   = (const float*)d_in[0];
    const float* boxes = (const float*)d_in[1];
    float* out = (float*)d_out;

    const int N = out_size / BATCHES;                 // 65536
    const int grid = BATCHES * (N / (TPB * PPT));     // 4 * 64 = 256 blocks
    pib_kernel<<<grid, TPB>>>(pts, boxes, out, N);
}

// round 2
// speedup vs baseline: 1.0039x; 1.0039x over previous
#include <cuda_runtime.h>

#define BATCHES 4
#define MBOX    128
#define TPB     64
#define PPT     4

__global__ __launch_bounds__(TPB)
void pib_kernel(const float* __restrict__ pts,
                const float* __restrict__ boxes,
                float* __restrict__ out,
                int N)
{
    // Box data in shared, SoA as two float4 per box:
    //   sA[m] = (cx, cy, cos, sin)
    //   sB[m] = (hx, hy, cz, hz)   (h = half dims)
    __shared__ float4 sA[MBOX];
    __shared__ float4 sB[MBOX];

    const int blocks_per_batch = gridDim.x / BATCHES;   // 256
    const int b   = blockIdx.x / blocks_per_batch;
    const int blk = blockIdx.x % blocks_per_batch;
    const int t   = threadIdx.x;

    #pragma unroll
    for (int m = t; m < MBOX; m += TPB) {
        const float* bx = boxes + ((size_t)b * MBOX + m) * 7;
        float cx = bx[0], cy = bx[1], cz = bx[2];
        float dxs = bx[3], dys = bx[4], dzs = bx[5];
        float rz = bx[6];
        float s, c;
        __sincosf(rz, &s, &c);
        sA[m] = make_float4(cx, cy, c, s);
        sB[m] = make_float4(0.5f * dxs, 0.5f * dys, cz, 0.5f * dzs);
    }
    __syncthreads();

    // 4 points per thread, contiguous, loaded as 3x float4 (48B, 16B-aligned)
    const int i0 = (blk * TPB + t) * PPT;
    const float4* p4 = reinterpret_cast<const float4*>(pts + ((size_t)b * N + i0) * 3);
    float4 q0 = p4[0], q1 = p4[1], q2 = p4[2];
    float x0 = q0.x, y0 = q0.y, z0 = q0.z;
    float x1 = q0.w, y1 = q1.x, z1 = q1.y;
    float x2 = q1.z, y2 = q1.w, z2 = q2.x;
    float x3 = q2.y, y3 = q2.z, z3 = q2.w;

    int r0 = -1, r1 = -1, r2 = -1, r3 = -1;

    // Descending scan: last hit written wins == smallest box index ==
    // "first containing box". One SEL per test, branchless.
    // Math kept bitwise-identical to the validated round-1 form.
    #pragma unroll 4
    for (int m = MBOX - 1; m >= 0; --m) {
        float4 A  = sA[m];
        float4 Bv = sB[m];
        float c = A.z, s = A.w;
        {
            float dx = x0 - A.x, dy = y0 - A.y, dz = z0 - Bv.z;
            float lx = dx * c + dy * s;
            float ly = dy * c - dx * s;
            bool in = (fabsf(lx) <= Bv.x) & (fabsf(ly) <= Bv.y) & (fabsf(dz) <= Bv.w);
            r0 = in ? m : r0;
        }
        {
            float dx = x1 - A.x, dy = y1 - A.y, dz = z1 - Bv.z;
            float lx = dx * c + dy * s;
            float ly = dy * c - dx * s;
            bool in = (fabsf(lx) <= Bv.x) & (fabsf(ly) <= Bv.y) & (fabsf(dz) <= Bv.w);
            r1 = in ? m : r1;
        }
        {
            float dx = x2 - A.x, dy = y2 - A.y, dz = z2 - Bv.z;
            float lx = dx * c + dy * s;
            float ly = dy * c - dx * s;
            bool in = (fabsf(lx) <= Bv.x) & (fabsf(ly) <= Bv.y) & (fabsf(dz) <= Bv.w);
            r2 = in ? m : r2;
        }
        {
            float dx = x3 - A.x, dy = y3 - A.y, dz = z3 - Bv.z;
            float lx = dx * c + dy * s;
            float ly = dy * c - dx * s;
            bool in = (fabsf(lx) <= Bv.x) & (fabsf(ly) <= Bv.y) & (fabsf(dz) <= Bv.w);
            r3 = in ? m : r3;
        }
    }

    float4 o = make_float4((float)r0, (float)r1, (float)r2, (float)r3);
    *reinterpret_cast<float4*>(out + (size_t)b * N + i0) = o;
}

extern "C" void kernel_launch(void* const* d_in, const int* in_sizes, int n_in,
                              void* d_out, int out_size)
{
    const float* pts   = (const float*)d_in[0];
    const float* boxes = (const float*)d_in[1];
    float* out = (float*)d_out;

    const int N = out_size / BATCHES;                        // 65536
    const int grid = BATCHES * (N / (TPB * PPT));            // 4 * 256 = 1024 blocks
    pib_kernel<<<grid, TPB>>>(pts, boxes, out, N);
}

// round 4
// speedup vs baseline: 2.3558x; 2.3466x over previous
#include <cuda_runtime.h>

#define BATCHES 4
#define MBOX    128
#define TPB     256
#define GRIDW   16
#define NCELL   (GRIDW * GRIDW)
#define CAP     128   // == MBOX: overflow structurally impossible

__global__ __launch_bounds__(TPB)
void pib_binned(const float* __restrict__ pts,
                const float* __restrict__ boxes,
                float* __restrict__ out,
                int N)
{
    // Preprocessed boxes:
    //   sA[m] = (cx, cy, cos, sin)
    //   sB[m] = (hx, hy, cz, hz)
    __shared__ float4 sA[MBOX];
    __shared__ float4 sB[MBOX];
    __shared__ int    cnt[NCELL];
    __shared__ unsigned char lst[NCELL][CAP];

    const int bpb = gridDim.x / BATCHES;     // blocks per batch = 256
    const int b   = blockIdx.x / bpb;
    const int blk = blockIdx.x % bpb;
    const int t   = threadIdx.x;

    if (t < NCELL) cnt[t] = 0;
    __syncthreads();

    const float inv_cell = (float)GRIDW / 100.0f;   // 0.16
    const float org      = -50.0f;

    // ---- build: one thread per box ----
    if (t < MBOX) {
        const float* bx = boxes + ((size_t)b * MBOX + t) * 7;
        float cx = bx[0], cy = bx[1], cz = bx[2];
        float hx = 0.5f * bx[3], hy = 0.5f * bx[4], hz = 0.5f * bx[5];
        float s, c;
        __sincosf(bx[6], &s, &c);
        sA[t] = make_float4(cx, cy, c, s);
        sB[t] = make_float4(hx, hy, cz, hz);

        // Conservative AABB of the rotated footprint, inflated well past
        // any fp rounding slack in the in-box test (~1e-5).
        float ac = fabsf(c), as = fabsf(s);
        float ex = hx * ac + hy * as + 1e-3f;
        float ey = hx * as + hy * ac + 1e-3f;

        int xlo = min(max((int)floorf((cx - ex - org) * inv_cell), 0), GRIDW - 1);
        int xhi = min(max((int)floorf((cx + ex - org) * inv_cell), 0), GRIDW - 1);
        int ylo = min(max((int)floorf((cy - ey - org) * inv_cell), 0), GRIDW - 1);
        int yhi = min(max((int)floorf((cy + ey - org) * inv_cell), 0), GRIDW - 1);

        for (int yy = ylo; yy <= yhi; ++yy)
            for (int xx = xlo; xx <= xhi; ++xx) {
                int cell = yy * GRIDW + xx;
                int p = atomicAdd(&cnt[cell], 1);
                lst[cell][p] = (unsigned char)t;
            }
    }
    __syncthreads();

    // ---- query: one thread per point ----
    const int i = blk * TPB + t;
    const float* p = pts + ((size_t)b * N + i) * 3;
    float x = p[0], y = p[1], z = p[2];

    int ix = min(max((int)floorf((x - org) * inv_cell), 0), GRIDW - 1);
    int iy = min(max((int)floorf((y - org) * inv_cell), 0), GRIDW - 1);
    int cell = iy * GRIDW + ix;
    int n = cnt[cell];

    int best = MBOX;    // sentinel > any real index
    for (int j = 0; j < n; ++j) {
        int m = lst[cell][j];
        float4 A  = sA[m];
        float4 Bv = sB[m];
        // Bitwise-identical test math to the validated round-1 kernel.
        float dx = x - A.x, dy = y - A.y, dz = z - Bv.z;
        float lx = dx * A.z + dy * A.w;
        float ly = dy * A.z - dx * A.w;
        bool in = (fabsf(lx) <= Bv.x) & (fabsf(ly) <= Bv.y) & (fabsf(dz) <= Bv.w);
        int cand = in ? m : MBOX;
        best = min(best, cand);
    }

    out[(size_t)b * N + i] = (best == MBOX) ? -1.0f : (float)best;
}

extern "C" void kernel_launch(void* const* d_in, const int* in_sizes, int n_in,
                              void* d_out, int out_size)
{
    const float* pts   = (const float*)d_in[0];
    const float* boxes = (const float*)d_in[1];
    float* out = (float*)d_out;

    const int N = out_size / BATCHES;             // 65536
    const int grid = BATCHES * (N / TPB);         // 4 * 256 = 1024 blocks
    pib_binned<<<grid, TPB>>>(pts, boxes, out, N);
}